// round 5
// baseline (speedup 1.0000x reference)
#include <cuda_runtime.h>
#include <cstdint>

// Problem constants
#define BATCH   256
#define N0      4096
#define N1      4096
#define N2      4096
#define N3      1024

#define ROWS_PER_BLOCK 8
#define NB_W1 (N0 / ROWS_PER_BLOCK)
#define NB_W2 (N1 / ROWS_PER_BLOCK)
#define NB_W3 (N2 / ROWS_PER_BLOCK)

#define GROUPS  64            // batch groups of 4 (4x16-bit fields in u64)
#define SPLITS  4             // source splits per group
#define SRC_PER_SPLIT (N0 / SPLITS)   // 1024

// Routing tables as u16 (indices < 4096), 16B-aligned for uint4 staging.
__device__ __align__(16) unsigned short g_d1[N0];
__device__ __align__(16) unsigned short g_d2[N1];
__device__ __align__(16) unsigned short g_d3[N2];

// Packed partial histograms [group][bin] and per-group completion tickets.
// Zero at module load; the last split-block of each group re-zeros both after
// converting, so every run (correctness + each graph replay) starts clean.
__device__ unsigned long long g_scratch[GROUPS * N3];
__device__ int g_done[GROUPS];

// ---------------------------------------------------------------------------
// Row argmax, warp per row, 4x float4 streaming loads (evict-first: W has
// zero reuse). First-occurrence semantics (jnp.argmax).
// ---------------------------------------------------------------------------
__device__ __forceinline__ void argmax_row(const float* __restrict__ W,
                                           int row, int n_cols, int lane,
                                           unsigned short* __restrict__ out_idx)
{
    const float4* __restrict__ Wr =
        reinterpret_cast<const float4*>(W + (size_t)row * n_cols);
    const int n4 = n_cols >> 2;

    float best = -__int_as_float(0x7f800000);  // -inf
    int   bidx = 0;

    for (int i = lane; i < n4; i += 128) {
        float4 v[4];
        #pragma unroll
        for (int u = 0; u < 4; ++u) v[u] = __ldcs(&Wr[i + u * 32]);

        float g = -__int_as_float(0x7f800000);
        #pragma unroll
        for (int u = 0; u < 4; ++u)
            g = fmaxf(g, fmaxf(fmaxf(v[u].x, v[u].y), fmaxf(v[u].z, v[u].w)));

        if (g > best) {
            best = g;
            int idx = 0;
            // descending scan: last surviving write = smallest matching index
            #pragma unroll
            for (int u = 3; u >= 0; --u) {
                int base = (i + u * 32) << 2;
                if (v[u].w == g) idx = base + 3;
                if (v[u].z == g) idx = base + 2;
                if (v[u].y == g) idx = base + 1;
                if (v[u].x == g) idx = base;
            }
            bidx = idx;
        }
    }

    #pragma unroll
    for (int off = 16; off > 0; off >>= 1) {
        float ov = __shfl_down_sync(0xffffffffu, best, off);
        int   oi = __shfl_down_sync(0xffffffffu, bidx, off);
        if (ov > best || (ov == best && oi < bidx)) { best = ov; bidx = oi; }
    }
    if (lane == 0) out_idx[row] = (unsigned short)bidx;
}

__global__ void __launch_bounds__(256, 8) fused_argmax_kernel(
    const float* __restrict__ W1,
    const float* __restrict__ W2,
    const float* __restrict__ W3)
{
    const int warp = threadIdx.x >> 5;
    const int lane = threadIdx.x & 31;
    const int bid  = blockIdx.x;

    if (bid < NB_W1) {
        argmax_row(W1, bid * ROWS_PER_BLOCK + warp, N1, lane, g_d1);
    } else if (bid < NB_W1 + NB_W2) {
        argmax_row(W2, (bid - NB_W1) * ROWS_PER_BLOCK + warp, N2, lane, g_d2);
    } else {
        argmax_row(W3, (bid - NB_W1 - NB_W2) * ROWS_PER_BLOCK + warp, N3, lane, g_d3);
    }
}

// ---------------------------------------------------------------------------
// Scatter + fused convert. Block (g, p): batches [4g,4g+4), sources
// [1024p, 1024p+1024). Counts are 0..7, per-bin totals <= 4096*7 = 28672
// < 2^16, so the four 16-bit fields of the u64 never carry into each other.
// 1024 smem u64 atomics per block; partials merge to g_scratch via REDG.
// The LAST split-block of each group (atomic ticket) unpacks the merged
// histogram to the 4 float output rows and re-zeros scratch + ticket.
// ---------------------------------------------------------------------------
__global__ void __launch_bounds__(512) scatter_kernel(const int* __restrict__ x,
                                                      float* __restrict__ out)
{
    __shared__ unsigned short t1[N0];
    __shared__ unsigned short t2[N1];
    __shared__ unsigned short t3[N2];
    __shared__ unsigned long long hist[N3];
    __shared__ int s_last;

    const int tid = threadIdx.x;
    const int g   = blockIdx.x & (GROUPS - 1);
    const int p   = blockIdx.x >> 6;

    // Stage tables: 4096 u16 = 512 uint4 per table, one per thread.
    reinterpret_cast<uint4*>(t1)[tid] = reinterpret_cast<const uint4*>(g_d1)[tid];
    reinterpret_cast<uint4*>(t2)[tid] = reinterpret_cast<const uint4*>(g_d2)[tid];
    reinterpret_cast<uint4*>(t3)[tid] = reinterpret_cast<const uint4*>(g_d3)[tid];
    hist[tid]       = 0ull;
    hist[tid + 512] = 0ull;
    __syncthreads();

    // 2 consecutive sources x 4 batches per thread (int2 per batch, coalesced)
    const int s0 = p * SRC_PER_SPLIT + 2 * tid;
    int2 c0 = *reinterpret_cast<const int2*>(x + (size_t)(4 * g + 0) * N0 + s0);
    int2 c1 = *reinterpret_cast<const int2*>(x + (size_t)(4 * g + 1) * N0 + s0);
    int2 c2 = *reinterpret_cast<const int2*>(x + (size_t)(4 * g + 2) * N0 + s0);
    int2 c3 = *reinterpret_cast<const int2*>(x + (size_t)(4 * g + 3) * N0 + s0);

    int f0 = t3[t2[t1[s0]]];
    int f1 = t3[t2[t1[s0 + 1]]];

    unsigned long long v0 =
          (unsigned long long)(unsigned)c0.x
        | ((unsigned long long)(unsigned)c1.x << 16)
        | ((unsigned long long)(unsigned)c2.x << 32)
        | ((unsigned long long)(unsigned)c3.x << 48);
    unsigned long long v1 =
          (unsigned long long)(unsigned)c0.y
        | ((unsigned long long)(unsigned)c1.y << 16)
        | ((unsigned long long)(unsigned)c2.y << 32)
        | ((unsigned long long)(unsigned)c3.y << 48);

    if (v0) atomicAdd(&hist[f0], v0);
    if (v1) atomicAdd(&hist[f1], v1);

    __syncthreads();

    // Merge partials into the group's global scratch.
    unsigned long long h0 = hist[tid];
    unsigned long long h1 = hist[tid + 512];
    if (h0) atomicAdd(&g_scratch[g * N3 + tid],       h0);
    if (h1) atomicAdd(&g_scratch[g * N3 + tid + 512], h1);

    // Make merges visible, then take a ticket. Last block converts.
    __threadfence();
    if (tid == 0)
        s_last = (atomicAdd(&g_done[g], 1) == SPLITS - 1) ? 1 : 0;
    __syncthreads();

    if (s_last) {
        __threadfence();  // acquire side: order scratch reads after ticket
        #pragma unroll
        for (int half = 0; half < 2; ++half) {
            int j = tid + half * 512;
            unsigned long long v =
                *(volatile unsigned long long*)&g_scratch[g * N3 + j];
            g_scratch[g * N3 + j] = 0ull;  // re-zero for next replay

            float* __restrict__ ob = out + (size_t)(4 * g) * N3 + j;
            ob[0]      = (float)( v        & 0xFFFFull);
            ob[N3]     = (float)((v >> 16) & 0xFFFFull);
            ob[2 * N3] = (float)((v >> 32) & 0xFFFFull);
            ob[3 * N3] = (float)((v >> 48) & 0xFFFFull);
        }
        if (tid == 0) g_done[g] = 0;       // reset ticket for next replay
    }
}

// ---------------------------------------------------------------------------
// Launch
//   d_in[0] = x  (int32,   [256, 4096])
//   d_in[1] = W1 (float32, [4096, 4096])
//   d_in[2] = W2 (float32, [4096, 4096])
//   d_in[3] = W3 (float32, [4096, 1024])
//   d_out   = float32 [256, 1024]
// ---------------------------------------------------------------------------
extern "C" void kernel_launch(void* const* d_in, const int* in_sizes, int n_in,
                              void* d_out, int out_size)
{
    const int*   x  = (const int*)  d_in[0];
    const float* W1 = (const float*)d_in[1];
    const float* W2 = (const float*)d_in[2];
    const float* W3 = (const float*)d_in[3];
    float* out = (float*)d_out;

    fused_argmax_kernel<<<NB_W1 + NB_W2 + NB_W3, 256>>>(W1, W2, W3);
    scatter_kernel<<<GROUPS * SPLITS, 512>>>(x, out);
}

// round 6
// speedup vs baseline: 1.2393x; 1.2393x over previous
#include <cuda_runtime.h>
#include <cstdint>

// Problem constants
#define BATCH   256
#define N0      4096
#define N1      4096
#define N2      4096
#define N3      1024

#define ROWS_PER_BLOCK 8
#define NB_W1 (N0 / ROWS_PER_BLOCK)
#define NB_W2 (N1 / ROWS_PER_BLOCK)
#define NB_W3 (N2 / ROWS_PER_BLOCK)

#define GROUPS  128           // batch groups of 2 (2x16-bit fields in u32)
#define SPLITS  2             // source splits per group
#define SRC_PER_SPLIT (N0 / SPLITS)   // 2048

// Routing tables as u16 (indices < 4096), 16B-aligned for uint4 staging.
__device__ __align__(16) unsigned short g_d1[N0];
__device__ __align__(16) unsigned short g_d2[N1];
__device__ __align__(16) unsigned short g_d3[N2];

// Packed partial histograms [group][bin]. Zero at module load; convert_kernel
// re-zeros after reading, so correctness run + every graph replay start clean.
__device__ unsigned int g_scratch[GROUPS * N3];

// ---------------------------------------------------------------------------
// Row argmax — EXACT round-3 configuration (measured 26.2us, DRAM 74.8%).
// Warp per row, 8x-unrolled float4 loads. First-occurrence (jnp.argmax).
// ---------------------------------------------------------------------------
__device__ __forceinline__ void argmax_row(const float* __restrict__ W,
                                           int row, int n_cols, int lane,
                                           unsigned short* __restrict__ out_idx)
{
    const float4* __restrict__ Wr =
        reinterpret_cast<const float4*>(W + (size_t)row * n_cols);
    const int n4 = n_cols >> 2;

    float best = -__int_as_float(0x7f800000);  // -inf
    int   bidx = 0;

    for (int i = lane; i < n4; i += 256) {
        float4 v[8];
        #pragma unroll
        for (int u = 0; u < 8; ++u) v[u] = Wr[i + u * 32];

        float g = -__int_as_float(0x7f800000);
        #pragma unroll
        for (int u = 0; u < 8; ++u)
            g = fmaxf(g, fmaxf(fmaxf(v[u].x, v[u].y), fmaxf(v[u].z, v[u].w)));

        if (g > best) {
            best = g;
            int idx = 0;
            // descending scan: last surviving write = smallest matching index
            #pragma unroll
            for (int u = 7; u >= 0; --u) {
                int base = (i + u * 32) << 2;
                if (v[u].w == g) idx = base + 3;
                if (v[u].z == g) idx = base + 2;
                if (v[u].y == g) idx = base + 1;
                if (v[u].x == g) idx = base;
            }
            bidx = idx;
        }
    }

    #pragma unroll
    for (int off = 16; off > 0; off >>= 1) {
        float ov = __shfl_down_sync(0xffffffffu, best, off);
        int   oi = __shfl_down_sync(0xffffffffu, bidx, off);
        if (ov > best || (ov == best && oi < bidx)) { best = ov; bidx = oi; }
    }
    if (lane == 0) out_idx[row] = (unsigned short)bidx;
}

__global__ void __launch_bounds__(256) fused_argmax_kernel(
    const float* __restrict__ W1,
    const float* __restrict__ W2,
    const float* __restrict__ W3)
{
    const int warp = threadIdx.x >> 5;
    const int lane = threadIdx.x & 31;
    const int bid  = blockIdx.x;

    if (bid < NB_W1) {
        argmax_row(W1, bid * ROWS_PER_BLOCK + warp, N1, lane, g_d1);
    } else if (bid < NB_W1 + NB_W2) {
        argmax_row(W2, (bid - NB_W1) * ROWS_PER_BLOCK + warp, N2, lane, g_d2);
    } else {
        argmax_row(W3, (bid - NB_W1 - NB_W2) * ROWS_PER_BLOCK + warp, N3, lane, g_d3);
    }
}

// ---------------------------------------------------------------------------
// Scatter. Block (g, p): batches {2g, 2g+1}, sources [2048p, 2048p+2048).
// Counts 0..7, per-bin totals <= 28672 < 2^16 -> the two 16-bit fields of a
// u32 never carry. 2048 native u32 smem atomics per block. Partials merge to
// g_scratch with no-return global atomicAdd (no fences — the separate convert
// launch provides ordering).
// ---------------------------------------------------------------------------
__global__ void __launch_bounds__(512) scatter_kernel(const int* __restrict__ x)
{
    __shared__ unsigned short t1[N0];
    __shared__ unsigned short t2[N1];
    __shared__ unsigned short t3[N2];
    __shared__ unsigned int hist[N3];

    const int tid = threadIdx.x;
    const int g   = blockIdx.x & (GROUPS - 1);   // batch group
    const int p   = blockIdx.x >> 7;             // source split (0..1)

    // Stage tables: 4096 u16 = 512 uint4 per table, one per thread.
    reinterpret_cast<uint4*>(t1)[tid] = reinterpret_cast<const uint4*>(g_d1)[tid];
    reinterpret_cast<uint4*>(t2)[tid] = reinterpret_cast<const uint4*>(g_d2)[tid];
    reinterpret_cast<uint4*>(t3)[tid] = reinterpret_cast<const uint4*>(g_d3)[tid];
    hist[tid]       = 0u;
    hist[tid + 512] = 0u;
    __syncthreads();

    // 4 consecutive sources x 2 batches per thread (int4 per batch, coalesced)
    const int s0 = p * SRC_PER_SPLIT + 4 * tid;
    int4 c0 = *reinterpret_cast<const int4*>(x + (size_t)(2 * g)     * N0 + s0);
    int4 c1 = *reinterpret_cast<const int4*>(x + (size_t)(2 * g + 1) * N0 + s0);

    // 4 independent 3-hop LDS compose chains
    int f0 = t3[t2[t1[s0]]];
    int f1 = t3[t2[t1[s0 + 1]]];
    int f2 = t3[t2[t1[s0 + 2]]];
    int f3 = t3[t2[t1[s0 + 3]]];

    unsigned v0 = (unsigned)c0.x | ((unsigned)c1.x << 16);
    unsigned v1 = (unsigned)c0.y | ((unsigned)c1.y << 16);
    unsigned v2 = (unsigned)c0.z | ((unsigned)c1.z << 16);
    unsigned v3 = (unsigned)c0.w | ((unsigned)c1.w << 16);

    if (v0) atomicAdd(&hist[f0], v0);
    if (v1) atomicAdd(&hist[f1], v1);
    if (v2) atomicAdd(&hist[f2], v2);
    if (v3) atomicAdd(&hist[f3], v3);

    __syncthreads();

    // Merge partials into the group's global scratch (no return value -> REDG).
    unsigned h0 = hist[tid];
    unsigned h1 = hist[tid + 512];
    if (h0) atomicAdd(&g_scratch[g * N3 + tid],       h0);
    if (h1) atomicAdd(&g_scratch[g * N3 + tid + 512], h1);
}

// ---------------------------------------------------------------------------
// Unpack scratch -> float out, re-zero scratch for the next replay.
// Block g: group g (2 batches), 1024 bins, 512 threads x 2 bins.
// ---------------------------------------------------------------------------
__global__ void __launch_bounds__(512) convert_kernel(float* __restrict__ out)
{
    const int g   = blockIdx.x;
    const int tid = threadIdx.x;

    #pragma unroll
    for (int half = 0; half < 2; ++half) {
        int j = tid + half * 512;
        unsigned v = g_scratch[g * N3 + j];
        g_scratch[g * N3 + j] = 0u;

        out[(size_t)(2 * g)     * N3 + j] = (float)(v & 0xFFFFu);
        out[(size_t)(2 * g + 1) * N3 + j] = (float)(v >> 16);
    }
}

// ---------------------------------------------------------------------------
// Launch
//   d_in[0] = x  (int32,   [256, 4096])
//   d_in[1] = W1 (float32, [4096, 4096])
//   d_in[2] = W2 (float32, [4096, 4096])
//   d_in[3] = W3 (float32, [4096, 1024])
//   d_out   = float32 [256, 1024]
// ---------------------------------------------------------------------------
extern "C" void kernel_launch(void* const* d_in, const int* in_sizes, int n_in,
                              void* d_out, int out_size)
{
    const int*   x  = (const int*)  d_in[0];
    const float* W1 = (const float*)d_in[1];
    const float* W2 = (const float*)d_in[2];
    const float* W3 = (const float*)d_in[3];
    float* out = (float*)d_out;

    fused_argmax_kernel<<<NB_W1 + NB_W2 + NB_W3, 256>>>(W1, W2, W3);
    scatter_kernel<<<GROUPS * SPLITS, 512>>>(x);
    convert_kernel<<<GROUPS, 512>>>(out);
}

// round 7
// speedup vs baseline: 1.3921x; 1.1232x over previous
#include <cuda_runtime.h>
#include <cstdint>

// Problem constants
#define BATCH   256
#define N0      4096
#define N1      4096
#define N2      4096
#define N3      1024

#define ROWS_PER_BLOCK 8
#define NB_W1 (N0 / ROWS_PER_BLOCK)
#define NB_W2 (N1 / ROWS_PER_BLOCK)
#define NB_W3 (N2 / ROWS_PER_BLOCK)

#define GROUPS  128   // batch groups of 2 (2x16-bit fields per u32)

// Routing tables as u16 (indices < 4096), 16B-aligned for uint4 staging.
__device__ __align__(16) unsigned short g_d1[N0];
__device__ __align__(16) unsigned short g_d2[N1];
__device__ __align__(16) unsigned short g_d3[N2];

// ---------------------------------------------------------------------------
// Row argmax — EXACT round-3 configuration (measured 25.9-26.2us, DRAM ~75%).
// Warp per row, 8x-unrolled float4 loads. First-occurrence (jnp.argmax).
// ---------------------------------------------------------------------------
__device__ __forceinline__ void argmax_row(const float* __restrict__ W,
                                           int row, int n_cols, int lane,
                                           unsigned short* __restrict__ out_idx)
{
    const float4* __restrict__ Wr =
        reinterpret_cast<const float4*>(W + (size_t)row * n_cols);
    const int n4 = n_cols >> 2;

    float best = -__int_as_float(0x7f800000);  // -inf
    int   bidx = 0;

    for (int i = lane; i < n4; i += 256) {
        float4 v[8];
        #pragma unroll
        for (int u = 0; u < 8; ++u) v[u] = Wr[i + u * 32];

        float g = -__int_as_float(0x7f800000);
        #pragma unroll
        for (int u = 0; u < 8; ++u)
            g = fmaxf(g, fmaxf(fmaxf(v[u].x, v[u].y), fmaxf(v[u].z, v[u].w)));

        if (g > best) {
            best = g;
            int idx = 0;
            // descending scan: last surviving write = smallest matching index
            #pragma unroll
            for (int u = 7; u >= 0; --u) {
                int base = (i + u * 32) << 2;
                if (v[u].w == g) idx = base + 3;
                if (v[u].z == g) idx = base + 2;
                if (v[u].y == g) idx = base + 1;
                if (v[u].x == g) idx = base;
            }
            bidx = idx;
        }
    }

    #pragma unroll
    for (int off = 16; off > 0; off >>= 1) {
        float ov = __shfl_down_sync(0xffffffffu, best, off);
        int   oi = __shfl_down_sync(0xffffffffu, bidx, off);
        if (ov > best || (ov == best && oi < bidx)) { best = ov; bidx = oi; }
    }
    if (lane == 0) out_idx[row] = (unsigned short)bidx;
}

__global__ void __launch_bounds__(256) fused_argmax_kernel(
    const float* __restrict__ W1,
    const float* __restrict__ W2,
    const float* __restrict__ W3)
{
    const int warp = threadIdx.x >> 5;
    const int lane = threadIdx.x & 31;
    const int bid  = blockIdx.x;

    if (bid < NB_W1) {
        argmax_row(W1, bid * ROWS_PER_BLOCK + warp, N1, lane, g_d1);
    } else if (bid < NB_W1 + NB_W2) {
        argmax_row(W2, (bid - NB_W1) * ROWS_PER_BLOCK + warp, N2, lane, g_d2);
    } else {
        argmax_row(W3, (bid - NB_W1 - NB_W2) * ROWS_PER_BLOCK + warp, N3, lane, g_d3);
    }
}

// ---------------------------------------------------------------------------
// Scatter, single kernel, no scratch/merge/fences.
// Block g handles batches {2g, 2g+1}: both batches' counts pack into the two
// 16-bit fields of one u32 (counts 0..7; per-bin totals <= 4096*7 = 28672
// < 2^16, so fields never carry). All 4096 sources per block -> 4096 smem u32
// atomics; 128 blocks = single wave, one block per SM.
// Direct unpack to the two float output rows at the end.
// ---------------------------------------------------------------------------
__global__ void __launch_bounds__(512) scatter_kernel(const int* __restrict__ x,
                                                      float* __restrict__ out)
{
    __shared__ unsigned short t1[N0];
    __shared__ unsigned short t2[N1];
    __shared__ unsigned short t3[N2];
    __shared__ unsigned int hist[N3];

    const int tid = threadIdx.x;
    const int g   = blockIdx.x;

    // Stage tables: 4096 u16 = 512 uint4 per table, one per thread.
    reinterpret_cast<uint4*>(t1)[tid] = reinterpret_cast<const uint4*>(g_d1)[tid];
    reinterpret_cast<uint4*>(t2)[tid] = reinterpret_cast<const uint4*>(g_d2)[tid];
    reinterpret_cast<uint4*>(t3)[tid] = reinterpret_cast<const uint4*>(g_d3)[tid];
    hist[tid]       = 0u;
    hist[tid + 512] = 0u;
    __syncthreads();

    const int* __restrict__ xa = x + (size_t)(2 * g)     * N0;
    const int* __restrict__ xb = x + (size_t)(2 * g + 1) * N0;

    // 8 sources per thread: 2 iterations x 4 consecutive sources x 2 batches.
    #pragma unroll
    for (int it = 0; it < 2; ++it) {
        const int s0 = 4 * (tid + it * 512);
        int4 c0 = *reinterpret_cast<const int4*>(xa + s0);
        int4 c1 = *reinterpret_cast<const int4*>(xb + s0);

        // 4 independent 3-hop LDS compose chains
        int f0 = t3[t2[t1[s0]]];
        int f1 = t3[t2[t1[s0 + 1]]];
        int f2 = t3[t2[t1[s0 + 2]]];
        int f3 = t3[t2[t1[s0 + 3]]];

        unsigned v0 = (unsigned)c0.x | ((unsigned)c1.x << 16);
        unsigned v1 = (unsigned)c0.y | ((unsigned)c1.y << 16);
        unsigned v2 = (unsigned)c0.z | ((unsigned)c1.z << 16);
        unsigned v3 = (unsigned)c0.w | ((unsigned)c1.w << 16);

        if (v0) atomicAdd(&hist[f0], v0);
        if (v1) atomicAdd(&hist[f1], v1);
        if (v2) atomicAdd(&hist[f2], v2);
        if (v3) atomicAdd(&hist[f3], v3);
    }

    __syncthreads();

    // Unpack to the two output rows (coalesced float stores).
    float* __restrict__ oa = out + (size_t)(2 * g)     * N3;
    float* __restrict__ ob = out + (size_t)(2 * g + 1) * N3;
    #pragma unroll
    for (int half = 0; half < 2; ++half) {
        int j = tid + half * 512;
        unsigned v = hist[j];
        oa[j] = (float)(v & 0xFFFFu);
        ob[j] = (float)(v >> 16);
    }
}

// ---------------------------------------------------------------------------
// Launch
//   d_in[0] = x  (int32,   [256, 4096])
//   d_in[1] = W1 (float32, [4096, 4096])
//   d_in[2] = W2 (float32, [4096, 4096])
//   d_in[3] = W3 (float32, [4096, 1024])
//   d_out   = float32 [256, 1024]
// ---------------------------------------------------------------------------
extern "C" void kernel_launch(void* const* d_in, const int* in_sizes, int n_in,
                              void* d_out, int out_size)
{
    const int*   x  = (const int*)  d_in[0];
    const float* W1 = (const float*)d_in[1];
    const float* W2 = (const float*)d_in[2];
    const float* W3 = (const float*)d_in[3];
    float* out = (float*)d_out;

    fused_argmax_kernel<<<NB_W1 + NB_W2 + NB_W3, 256>>>(W1, W2, W3);
    scatter_kernel<<<GROUPS, 512>>>(x, out);
}

// round 8
// speedup vs baseline: 1.4225x; 1.0219x over previous
#include <cuda_runtime.h>
#include <cstdint>

// Problem constants
#define BATCH   256
#define N0      4096
#define N1      4096
#define N2      4096
#define N3      1024

#define ROWS_PER_BLOCK 8
#define NB_W1 (N0 / ROWS_PER_BLOCK)
#define NB_W2 (N1 / ROWS_PER_BLOCK)
#define NB_W3 (N2 / ROWS_PER_BLOCK)

#define GROUPS  128   // batch groups of 2 (2x16-bit fields per u32)

// Routing tables as u16 (indices < 4096), 16B-aligned for uint4 staging.
__device__ __align__(16) unsigned short g_d1[N0];
__device__ __align__(16) unsigned short g_d2[N1];
__device__ __align__(16) unsigned short g_d3[N2];

// ---------------------------------------------------------------------------
// Row argmax — FROZEN round-3 configuration (measured 25.9-26.2us, DRAM ~75%).
// Warp per row, 8x-unrolled float4 loads. First-occurrence (jnp.argmax).
// ---------------------------------------------------------------------------
__device__ __forceinline__ void argmax_row(const float* __restrict__ W,
                                           int row, int n_cols, int lane,
                                           unsigned short* __restrict__ out_idx)
{
    const float4* __restrict__ Wr =
        reinterpret_cast<const float4*>(W + (size_t)row * n_cols);
    const int n4 = n_cols >> 2;

    float best = -__int_as_float(0x7f800000);  // -inf
    int   bidx = 0;

    for (int i = lane; i < n4; i += 256) {
        float4 v[8];
        #pragma unroll
        for (int u = 0; u < 8; ++u) v[u] = Wr[i + u * 32];

        float g = -__int_as_float(0x7f800000);
        #pragma unroll
        for (int u = 0; u < 8; ++u)
            g = fmaxf(g, fmaxf(fmaxf(v[u].x, v[u].y), fmaxf(v[u].z, v[u].w)));

        if (g > best) {
            best = g;
            int idx = 0;
            // descending scan: last surviving write = smallest matching index
            #pragma unroll
            for (int u = 7; u >= 0; --u) {
                int base = (i + u * 32) << 2;
                if (v[u].w == g) idx = base + 3;
                if (v[u].z == g) idx = base + 2;
                if (v[u].y == g) idx = base + 1;
                if (v[u].x == g) idx = base;
            }
            bidx = idx;
        }
    }

    #pragma unroll
    for (int off = 16; off > 0; off >>= 1) {
        float ov = __shfl_down_sync(0xffffffffu, best, off);
        int   oi = __shfl_down_sync(0xffffffffu, bidx, off);
        if (ov > best || (ov == best && oi < bidx)) { best = ov; bidx = oi; }
    }
    if (lane == 0) out_idx[row] = (unsigned short)bidx;
}

__global__ void __launch_bounds__(256) fused_argmax_kernel(
    const float* __restrict__ W1,
    const float* __restrict__ W2,
    const float* __restrict__ W3)
{
    const int warp = threadIdx.x >> 5;
    const int lane = threadIdx.x & 31;
    const int bid  = blockIdx.x;

    if (bid < NB_W1) {
        argmax_row(W1, bid * ROWS_PER_BLOCK + warp, N1, lane, g_d1);
    } else if (bid < NB_W1 + NB_W2) {
        argmax_row(W2, (bid - NB_W1) * ROWS_PER_BLOCK + warp, N2, lane, g_d2);
    } else {
        argmax_row(W3, (bid - NB_W1 - NB_W2) * ROWS_PER_BLOCK + warp, N3, lane, g_d3);
    }
}

// ---------------------------------------------------------------------------
// Scatter, single kernel. Block g handles batches {2g, 2g+1}: counts pack
// into the two 16-bit fields of one u32 (counts 0..7; per-bin totals <=
// 4096*7 = 28672 < 2^16 -> no carries). 1024 threads/block (32 warps) to
// cover LDS-chain and atomic latency; TWO sub-histograms (one per half of
// the warps) halve atomic conflict degree, merged at writeout.
// ---------------------------------------------------------------------------
__global__ void __launch_bounds__(1024) scatter_kernel(const int* __restrict__ x,
                                                       float* __restrict__ out)
{
    __shared__ unsigned short t1[N0];
    __shared__ unsigned short t2[N1];
    __shared__ unsigned short t3[N2];
    __shared__ unsigned int hist[2][N3];

    const int tid = threadIdx.x;
    const int g   = blockIdx.x;

    // Stage tables: 3 x 512 uint4 over 1024 threads.
    if (tid < 512) {
        reinterpret_cast<uint4*>(t1)[tid] = reinterpret_cast<const uint4*>(g_d1)[tid];
        reinterpret_cast<uint4*>(t3)[tid] = reinterpret_cast<const uint4*>(g_d3)[tid];
    } else {
        reinterpret_cast<uint4*>(t2)[tid - 512] =
            reinterpret_cast<const uint4*>(g_d2)[tid - 512];
    }
    hist[0][tid & (N3 - 1)] = 0u;            // tid 0..1023 covers copy 0
    hist[1][tid & (N3 - 1)] = 0u;            // and copy 1
    __syncthreads();

    const int* __restrict__ xa = x + (size_t)(2 * g)     * N0;
    const int* __restrict__ xb = x + (size_t)(2 * g + 1) * N0;

    // 4 consecutive sources x 2 batches per thread (one int4 per batch row).
    const int s0 = 4 * tid;
    int4 c0 = *reinterpret_cast<const int4*>(xa + s0);
    int4 c1 = *reinterpret_cast<const int4*>(xb + s0);

    // 4 independent 3-hop LDS compose chains
    int f0 = t3[t2[t1[s0]]];
    int f1 = t3[t2[t1[s0 + 1]]];
    int f2 = t3[t2[t1[s0 + 2]]];
    int f3 = t3[t2[t1[s0 + 3]]];

    unsigned v0 = (unsigned)c0.x | ((unsigned)c1.x << 16);
    unsigned v1 = (unsigned)c0.y | ((unsigned)c1.y << 16);
    unsigned v2 = (unsigned)c0.z | ((unsigned)c1.z << 16);
    unsigned v3 = (unsigned)c0.w | ((unsigned)c1.w << 16);

    unsigned int* h = hist[(tid >> 9) & 1];  // warps 0-15 -> copy 0, 16-31 -> 1
    if (v0) atomicAdd(&h[f0], v0);
    if (v1) atomicAdd(&h[f1], v1);
    if (v2) atomicAdd(&h[f2], v2);
    if (v3) atomicAdd(&h[f3], v3);

    __syncthreads();

    // Merge sub-histograms + unpack to the two output rows (1024 threads,
    // one bin each).
    float* __restrict__ oa = out + (size_t)(2 * g)     * N3;
    float* __restrict__ ob = out + (size_t)(2 * g + 1) * N3;
    unsigned v = hist[0][tid] + hist[1][tid];
    oa[tid] = (float)(v & 0xFFFFu);
    ob[tid] = (float)(v >> 16);
}

// ---------------------------------------------------------------------------
// Launch
//   d_in[0] = x  (int32,   [256, 4096])
//   d_in[1] = W1 (float32, [4096, 4096])
//   d_in[2] = W2 (float32, [4096, 4096])
//   d_in[3] = W3 (float32, [4096, 1024])
//   d_out   = float32 [256, 1024]
// ---------------------------------------------------------------------------
extern "C" void kernel_launch(void* const* d_in, const int* in_sizes, int n_in,
                              void* d_out, int out_size)
{
    const int*   x  = (const int*)  d_in[0];
    const float* W1 = (const float*)d_in[1];
    const float* W2 = (const float*)d_in[2];
    const float* W3 = (const float*)d_in[3];
    float* out = (float*)d_out;

    fused_argmax_kernel<<<NB_W1 + NB_W2 + NB_W3, 256>>>(W1, W2, W3);
    scatter_kernel<<<GROUPS, 1024>>>(x, out);
}